// round 1
// baseline (speedup 1.0000x reference)
#include <cuda_runtime.h>
#include <cuda_bf16.h>
#include <math.h>

#define BATCH 2
#define SEQ 4096
#define HID 1024
#define FEAT 3072
#define NGOLD 50
#define MAX_SPAN_LEN 30
#define BANDW 32
#define MAXK 819
#define ROWS (BATCH*SEQ)     /* 8192 */

/* output layout (all float32): starts[B,MAXK] | ends[B,MAXK] | span_mask[B,MAXK]
   | sequence_output[B,S,H] | cost[B] */
#define OFF_STARTS 0
#define OFF_ENDS   (BATCH*MAXK)
#define OFF_MASK   (2*BATCH*MAXK)
#define OFF_SEQ    (3*BATCH*MAXK)
#define OFF_COST   (OFF_SEQ + (size_t)ROWS*HID)

/* ---------------- device scratch (static, no allocations) ---------------- */
__device__ float  g_start[(size_t)ROWS*FEAT];
__device__ float  g_end  [(size_t)ROWS*FEAT];
__device__ float  g_temp [(size_t)ROWS*FEAT];
__device__ float  g_band [(size_t)BATCH*SEQ*BANDW];
__device__ float  g_sl[ROWS];
__device__ float  g_el[ROWS];
__device__ double g_junk[BATCH];
__device__ double g_mm[BATCH];
__device__ int    g_selbuf[BATCH][2048];
__device__ int    g_eqbuf [BATCH][1024];

/* ---------------- init ---------------- */
__global__ void init_kernel() {
    int t = threadIdx.x;
    if (t < BATCH) { g_junk[t] = 0.0; g_mm[t] = 0.0; }
}

/* ---------------- fp32 tiled GEMM: C = act(A[M,K] @ B[K,N] + bias) ---------------- */
template<bool GELU>
__global__ __launch_bounds__(256)
void gemm_kernel(const float* __restrict__ A, const float* __restrict__ B,
                 const float* __restrict__ bias, float* __restrict__ C,
                 int M, int N, int K)
{
    __shared__ float As[16][128];
    __shared__ float Bs[16][132];

    int tid = threadIdx.x;
    int bx = blockIdx.x, by = blockIdx.y;
    const float* Ablk = A + (size_t)by * 128 * K;
    const float* Bblk = B + (size_t)bx * 128;
    int ty = tid >> 4, tx = tid & 15;

    int arow = tid >> 2;        /* 0..63 */
    int ac4  = tid & 3;         /* 0..3  */
    int brow = tid >> 5;        /* 0..7  */
    int bc4  = tid & 31;        /* 0..31 */

    float acc[8][8];
#pragma unroll
    for (int i = 0; i < 8; ++i)
#pragma unroll
        for (int j = 0; j < 8; ++j) acc[i][j] = 0.0f;

    int nk = K >> 4;
    float4 ra0 = *(const float4*)(Ablk + (size_t)arow * K + ac4 * 4);
    float4 ra1 = *(const float4*)(Ablk + (size_t)(arow + 64) * K + ac4 * 4);
    float4 rb0 = *(const float4*)(Bblk + (size_t)brow * N + bc4 * 4);
    float4 rb1 = *(const float4*)(Bblk + (size_t)(brow + 8) * N + bc4 * 4);

    for (int t = 0; t < nk; ++t) {
        As[ac4*4+0][arow] = ra0.x; As[ac4*4+1][arow] = ra0.y;
        As[ac4*4+2][arow] = ra0.z; As[ac4*4+3][arow] = ra0.w;
        As[ac4*4+0][arow+64] = ra1.x; As[ac4*4+1][arow+64] = ra1.y;
        As[ac4*4+2][arow+64] = ra1.z; As[ac4*4+3][arow+64] = ra1.w;
        *(float4*)&Bs[brow][bc4*4]   = rb0;
        *(float4*)&Bs[brow+8][bc4*4] = rb1;
        __syncthreads();

        if (t + 1 < nk) {
            int k0 = (t + 1) << 4;
            ra0 = *(const float4*)(Ablk + (size_t)arow * K + k0 + ac4 * 4);
            ra1 = *(const float4*)(Ablk + (size_t)(arow + 64) * K + k0 + ac4 * 4);
            rb0 = *(const float4*)(Bblk + (size_t)(k0 + brow) * N + bc4 * 4);
            rb1 = *(const float4*)(Bblk + (size_t)(k0 + brow + 8) * N + bc4 * 4);
        }

#pragma unroll
        for (int k = 0; k < 16; ++k) {
            float4 a0 = *(const float4*)&As[k][ty*8];
            float4 a1 = *(const float4*)&As[k][ty*8+4];
            float4 b0 = *(const float4*)&Bs[k][tx*8];
            float4 b1 = *(const float4*)&Bs[k][tx*8+4];
            float av[8] = {a0.x,a0.y,a0.z,a0.w,a1.x,a1.y,a1.z,a1.w};
            float bv[8] = {b0.x,b0.y,b0.z,b0.w,b1.x,b1.y,b1.z,b1.w};
#pragma unroll
            for (int i = 0; i < 8; ++i)
#pragma unroll
                for (int j = 0; j < 8; ++j)
                    acc[i][j] = fmaf(av[i], bv[j], acc[i][j]);
        }
        __syncthreads();
    }

    int crow = by * 128 + ty * 8;
    int ccol = bx * 128 + tx * 8;
#pragma unroll
    for (int i = 0; i < 8; ++i) {
#pragma unroll
        for (int j = 0; j < 8; ++j) {
            float v = acc[i][j] + bias[ccol + j];
            if (GELU) v = 0.5f * v * (1.0f + erff(v * 0.70710678118654752440f));
            C[(size_t)(crow + i) * N + ccol + j] = v;
        }
    }
}

/* ---------------- LayerNorm (in-place) + dot with w -> logits ---------------- */
__global__ __launch_bounds__(256)
void ln_dot_kernel(float* __restrict__ h, const float* __restrict__ gamma,
                   const float* __restrict__ beta, const float* __restrict__ wv,
                   const float* __restrict__ bsc, float* __restrict__ logits)
{
    __shared__ double red[256];
    int r = blockIdx.x, tid = threadIdx.x;
    float* row = h + (size_t)r * FEAT;
    const int PER = FEAT / 256;   /* 12 */
    float v[PER];
    double s = 0.0;
#pragma unroll
    for (int i = 0; i < PER; ++i) { v[i] = row[tid + i * 256]; s += (double)v[i]; }
    red[tid] = s; __syncthreads();
    for (int o = 128; o > 0; o >>= 1) { if (tid < o) red[tid] += red[tid + o]; __syncthreads(); }
    double mu = red[0] / FEAT;
    __syncthreads();

    double vs = 0.0;
#pragma unroll
    for (int i = 0; i < PER; ++i) { double d = (double)v[i] - mu; vs += d * d; }
    red[tid] = vs; __syncthreads();
    for (int o = 128; o > 0; o >>= 1) { if (tid < o) red[tid] += red[tid + o]; __syncthreads(); }
    float var = (float)(red[0] / FEAT);
    float rstd = rsqrtf(var + 1e-5f);
    float fmu = (float)mu;
    __syncthreads();

    double dot = 0.0;
#pragma unroll
    for (int i = 0; i < PER; ++i) {
        int f = tid + i * 256;
        float y = (v[i] - fmu) * rstd * gamma[f] + beta[f];
        row[f] = y;
        dot += (double)y * (double)wv[f];
    }
    red[tid] = dot; __syncthreads();
    for (int o = 128; o > 0; o >>= 1) { if (tid < o) red[tid] += red[tid + o]; __syncthreads(); }
    if (tid == 0) logits[r] = (float)red[0] + bsc[0];
}

/* ---------------- band joint + fused junk-BCE accumulation ---------------- */
__device__ __forceinline__ float bce0_term(float l) {
    /* replicate -clip(log1p(-sigmoid(l)), -100) in f32 */
    float p = 1.0f / (1.0f + expf(-l));
    float t = -log1pf(-p);          /* +inf if p rounds to 1 */
    return fminf(t, 100.0f);
}

__global__ __launch_bounds__(256)
void band_kernel(const int* __restrict__ am)
{
    __shared__ float As[32][33];    /* [k][r]  temp rows  */
    __shared__ float Bs[32][65];    /* [k][c]  end rows   */
    __shared__ double red[256];

    int b  = blockIdx.y;
    int i0 = blockIdx.x * 32;
    int tid = threadIdx.x;
    const float* Tm = g_temp + (size_t)b * SEQ * FEAT;
    const float* En = g_end  + (size_t)b * SEQ * FEAT;

    int ar  = tid >> 3;     /* 0..31 */
    int ac4 = tid & 7;      /* 0..7  */
    int r  = tid & 31;
    int cb = (tid >> 5) * 8;

    float acc[8];
#pragma unroll
    for (int i = 0; i < 8; ++i) acc[i] = 0.0f;

    for (int k0 = 0; k0 < FEAT; k0 += 32) {
        float4 a = *(const float4*)(Tm + (size_t)(i0 + ar) * FEAT + k0 + ac4 * 4);
        As[ac4*4+0][ar] = a.x; As[ac4*4+1][ar] = a.y;
        As[ac4*4+2][ar] = a.z; As[ac4*4+3][ar] = a.w;
#pragma unroll
        for (int h = 0; h < 2; ++h) {
            int row = ar + h * 32;
            int j = i0 + row;
            float4 bv = make_float4(0.f, 0.f, 0.f, 0.f);
            if (j < SEQ) bv = *(const float4*)(En + (size_t)j * FEAT + k0 + ac4 * 4);
            Bs[ac4*4+0][row] = bv.x; Bs[ac4*4+1][row] = bv.y;
            Bs[ac4*4+2][row] = bv.z; Bs[ac4*4+3][row] = bv.w;
        }
        __syncthreads();
#pragma unroll
        for (int k = 0; k < 32; ++k) {
            float av = As[k][r];
#pragma unroll
            for (int cc = 0; cc < 8; ++cc)
                acc[cc] = fmaf(av, Bs[k][cb + cc], acc[cc]);
        }
        __syncthreads();
    }

    int i = i0 + r;
    float sli = g_sl[b * SEQ + i];
    int ami = am[b * SEQ + i];
    double tsum = 0.0, wsum = 0.0;
    const float NEGINF = __int_as_float(0xff800000);
#pragma unroll
    for (int cc = 0; cc < 8; ++cc) {
        int c = cb + cc;
        int d = c - r;
        int j = i0 + c;
        if (d >= 0 && d < BANDW) {
            float val = NEGINF;
            if (d < MAX_SPAN_LEN && j < SEQ) {
                float l = acc[cc] + sli + g_el[b * SEQ + j];
                l = fminf(fmaxf(l, -10000.0f), 10000.0f);
                val = l;
                float w = (float)(ami * am[b * SEQ + j]);
                tsum += (double)(bce0_term(l) * w);
                wsum += (double)w;
            }
            g_band[((size_t)b * SEQ + i) * BANDW + d] = val;
        }
    }
    red[tid] = tsum; __syncthreads();
    for (int o = 128; o > 0; o >>= 1) { if (tid < o) red[tid] += red[tid + o]; __syncthreads(); }
    if (tid == 0) atomicAdd(&g_junk[b], red[0]);
    __syncthreads();
    red[tid] = wsum; __syncthreads();
    for (int o = 128; o > 0; o >>= 1) { if (tid < o) red[tid] += red[tid + o]; __syncthreads(); }
    if (tid == 0) atomicAdd(&g_mm[b], red[0]);
}

/* ---------------- exact top-k (radix select) + sort + index outputs ---------------- */
__device__ __forceinline__ unsigned f2ord(float f) {
    unsigned u = __float_as_uint(f);
    return (u & 0x80000000u) ? ~u : (u | 0x80000000u);
}

__global__ __launch_bounds__(1024)
void select_kernel(const int* __restrict__ am, float* __restrict__ out)
{
    int b = blockIdx.x;
    int tid = threadIdx.x;
    const float* band = g_band + (size_t)b * SEQ * BANDW;
    const int N = SEQ * BANDW;

    __shared__ unsigned hist[256];
    __shared__ unsigned s_prefix, s_rem;
    __shared__ int arr[1024];
    __shared__ int s_nA, s_nE;

    /* lens -> k (replicating int((float)lens * 0.2f)) */
    int ls = 0;
    for (int i = tid; i < SEQ; i += 1024) ls += am[b * SEQ + i];
    arr[tid] = ls; __syncthreads();
    for (int o = 512; o > 0; o >>= 1) { if (tid < o) arr[tid] += arr[tid + o]; __syncthreads(); }
    int lens = arr[0];
    __syncthreads();
    int k = (int)((float)lens * 0.2f);
    if (k > MAXK) k = MAXK;
    if (k < 0) k = 0;

    /* 4-pass MSB radix select for the k-th largest ordered key */
    unsigned prefix = 0, rem = (unsigned)k;
    for (int shift = 24; shift >= 0; shift -= 8) {
        if (tid < 256) hist[tid] = 0u;
        __syncthreads();
        for (int idx = tid; idx < N; idx += 1024) {
            unsigned u = f2ord(band[idx]);
            if (shift == 24 || (u >> (shift + 8)) == (prefix >> (shift + 8)))
                atomicAdd(&hist[(u >> shift) & 255u], 1u);
        }
        __syncthreads();
        if (tid == 0) {
            unsigned remv = rem, pf = prefix;
            for (int bin = 255; bin >= 0; --bin) {
                unsigned c = hist[bin];
                if (c >= remv) { pf |= ((unsigned)bin) << shift; break; }
                remv -= c;
            }
            s_prefix = pf; s_rem = remv;
        }
        __syncthreads();
        prefix = s_prefix; rem = s_rem;
        __syncthreads();
    }
    unsigned thr = prefix;

    if (tid == 0) { s_nA = 0; s_nE = 0; }
    __syncthreads();
    for (int idx = tid; idx < N; idx += 1024) {
        unsigned u = f2ord(band[idx]);
        if (u > thr) {
            int p = atomicAdd(&s_nA, 1);
            if (p < 2048) {
                int i = idx >> 5, d = idx & 31;
                g_selbuf[b][p] = i * SEQ + i + d;
            }
        } else if (u == thr) {
            int p = atomicAdd(&s_nE, 1);
            if (p < 1024) {
                int i = idx >> 5, d = idx & 31;
                g_eqbuf[b][p] = i * SEQ + i + d;
            }
        }
    }
    __syncthreads();
    int nA = s_nA;
    int need = k - nA;
    if (tid == 0 && need > 0) {
        int ne = s_nE; if (ne > 1024) ne = 1024;
        for (int t = 0; t < need; ++t) {  /* jax tie-break: lowest flat index first */
            int best = -1, bv = 0x7fffffff;
            for (int q = 0; q < ne; ++q) {
                int v = g_eqbuf[b][q];
                if (v < bv) { bv = v; best = q; }
            }
            if (best >= 0) { g_eqbuf[b][best] = 0x7fffffff; g_selbuf[b][nA + t] = bv; }
        }
    }
    __syncthreads();

    /* idx array: k selected, pad with S*S-1, sort ascending, map S*S-1 -> 0 */
    arr[tid] = (tid < k) ? g_selbuf[b][tid]
             : ((tid < MAXK) ? (SEQ * SEQ - 1) : 0x7fffffff);
    __syncthreads();
    for (unsigned kk = 2; kk <= 1024; kk <<= 1) {
        for (unsigned j = kk >> 1; j > 0; j >>= 1) {
            unsigned ixj = tid ^ j;
            if (ixj > (unsigned)tid) {
                int a0 = arr[tid], a1 = arr[ixj];
                bool up = ((tid & kk) == 0);
                if ((a0 > a1) == up) { arr[tid] = a1; arr[ixj] = a0; }
            }
            __syncthreads();
        }
    }
    if (tid < MAXK) {
        int v = arr[tid];
        if (v == SEQ * SEQ - 1) v = 0;
        out[OFF_STARTS + b * MAXK + tid] = (float)(v / SEQ);
        out[OFF_ENDS   + b * MAXK + tid] = (float)(v % SEQ);
        out[OFF_MASK   + b * MAXK + tid] = (tid < k) ? 1.0f : 0.0f;
    }
}

/* ---------------- gold cost + junk adjustment -> cost_is_mention ---------------- */
__global__ void gold_kernel(const void* __restrict__ gold_raw,
                            const float* __restrict__ gm_mask,
                            const int* __restrict__ am,
                            float* __restrict__ out)
{
    if (threadIdx.x != 0) return;
    int b = blockIdx.x;
    const int* g32 = (const int*)gold_raw;
    const long long* g64 = (const long long*)gold_raw;

    /* detect int32 vs int64 gold dtype: int64 => all high words of first values are 0 */
    bool is64 = true;
    for (int w = 1; w < 200; w += 2) if (g32[w] != 0) { is64 = false; break; }

    int gs[NGOLD], ge[NGOLD];
    long long tot = 0;
    for (int g = 0; g < NGOLD; ++g) {
        int base = (b * NGOLD + g) * 2;
        long long a, e;
        if (is64) { a = g64[base]; e = g64[base + 1]; }
        else      { a = g32[base]; e = g32[base + 1]; }
        gs[g] = (int)a; ge[g] = (int)e; tot += a + e;
    }
    bool has_gold = (tot > 0);

    double gsum = 0.0, gmsum = 0.0;
    for (int g = 0; g < NGOLD; ++g) {
        float gmv = gm_mask[b * NGOLD + g];
        gmsum += (double)gmv;
        float term;
        if (gmv != 0.0f) {
            int d = ge[g] - gs[g];
            if (d >= 0 && d < MAX_SPAN_LEN) {
                float l = g_band[((size_t)b * SEQ + gs[g]) * BANDW + d];
                float p = (1.0f / (1.0f + expf(-l))) * gmv;
                float lp = logf(p);              /* -inf if p underflows to 0 */
                term = fminf(-lp, 100.0f);
            } else {
                term = 100.0f;                   /* masked logit -> p=0 -> clip at 100 */
            }
        } else term = 0.0f;
        gsum += (double)term;
    }
    double cost_gold = (has_gold && gmsum > 0.0) ? gsum / gmsum : 0.0;

    double sub = 0.0;
    if (has_gold) {
        for (int g = 0; g < NGOLD; ++g) {
            int d = ge[g] - gs[g];
            if (d < 0 || d >= MAX_SPAN_LEN) continue;
            if (gs[g] == 0 && ge[g] == 0) continue;     /* (0,0) restored */
            bool dup = false;
            for (int q = 0; q < g; ++q)
                if (gs[q] == gs[g] && ge[q] == ge[g]) { dup = true; break; }
            if (dup) continue;
            float l = g_band[((size_t)b * SEQ + gs[g]) * BANDW + d];
            float w = (float)(am[b * SEQ + gs[g]] * am[b * SEQ + ge[g]]);
            sub += (double)(bce0_term(l) * w);
        }
    }
    double cost_junk = (g_junk[b] - sub) / g_mm[b];
    out[OFF_COST + b] = (float)(cost_gold + cost_junk);
}

/* ---------------- host launcher ---------------- */
extern "C" void kernel_launch(void* const* d_in, const int* in_sizes, int n_in,
                              void* d_out, int out_size)
{
    const float* seq     = (const float*)d_in[0];
    const int*   am      = (const int*)  d_in[1];
    const void*  gold    =               d_in[2];
    const float* gmask   = (const float*)d_in[3];
    const float* Ws      = (const float*)d_in[4];
    const float* bs      = (const float*)d_in[5];
    const float* gsv     = (const float*)d_in[6];
    const float* betas   = (const float*)d_in[7];
    const float* We      = (const float*)d_in[8];
    const float* be      = (const float*)d_in[9];
    const float* gev     = (const float*)d_in[10];
    const float* betae   = (const float*)d_in[11];
    const float* w_start = (const float*)d_in[12];
    const float* b_start = (const float*)d_in[13];
    const float* w_end   = (const float*)d_in[14];
    const float* b_end   = (const float*)d_in[15];
    const float* W_s2e   = (const float*)d_in[16];
    const float* b_s2e   = (const float*)d_in[17];
    float* out = (float*)d_out;

    float *pstart, *pend, *ptemp, *psl, *pel;
    cudaGetSymbolAddress((void**)&pstart, g_start);
    cudaGetSymbolAddress((void**)&pend,   g_end);
    cudaGetSymbolAddress((void**)&ptemp,  g_temp);
    cudaGetSymbolAddress((void**)&psl,    g_sl);
    cudaGetSymbolAddress((void**)&pel,    g_el);

    init_kernel<<<1, 32>>>();

    dim3 gg(FEAT / 128, ROWS / 128);
    gemm_kernel<true><<<gg, 256>>>(seq, Ws, bs, pstart, ROWS, FEAT, HID);
    gemm_kernel<true><<<gg, 256>>>(seq, We, be, pend,   ROWS, FEAT, HID);

    ln_dot_kernel<<<ROWS, 256>>>(pstart, gsv, betas, w_start, b_start, psl);
    ln_dot_kernel<<<ROWS, 256>>>(pend,   gev, betae, w_end,   b_end,   pel);

    gemm_kernel<false><<<gg, 256>>>(pstart, W_s2e, b_s2e, ptemp, ROWS, FEAT, FEAT);

    band_kernel<<<dim3(SEQ / 32, BATCH), 256>>>(am);
    select_kernel<<<BATCH, 1024>>>(am, out);
    gold_kernel<<<BATCH, 1>>>(gold, gmask, am, out);

    cudaMemcpyAsync(out + OFF_SEQ, seq, (size_t)ROWS * HID * sizeof(float),
                    cudaMemcpyDeviceToDevice, 0);
}

// round 2
// speedup vs baseline: 1.2394x; 1.2394x over previous
#include <cuda_runtime.h>
#include <cuda_bf16.h>
#include <math.h>

#define BATCH 2
#define SEQ 4096
#define HID 1024
#define FEAT 3072
#define NGOLD 50
#define MAX_SPAN_LEN 30
#define BANDW 32
#define MAXK 819
#define ROWS (BATCH*SEQ)     /* 8192 */

/* output layout (all float32): starts[B,MAXK] | ends[B,MAXK] | span_mask[B,MAXK]
   | sequence_output[B,S,H] | cost[B] */
#define OFF_STARTS 0
#define OFF_ENDS   (BATCH*MAXK)
#define OFF_MASK   (2*BATCH*MAXK)
#define OFF_SEQ    (3*BATCH*MAXK)
#define OFF_COST   (OFF_SEQ + (size_t)ROWS*HID)

/* ---------------- device scratch (static, no allocations) ---------------- */
__device__ float  g_start[(size_t)ROWS*FEAT];
__device__ float  g_end  [(size_t)ROWS*FEAT];
__device__ float  g_temp [(size_t)ROWS*FEAT];
__device__ float  g_band [(size_t)BATCH*SEQ*BANDW];
__device__ float  g_sl[ROWS];
__device__ float  g_el[ROWS];
__device__ double g_junk[BATCH];
__device__ double g_mm[BATCH];
__device__ int    g_selbuf[BATCH][2048];
__device__ int    g_eqbuf [BATCH][1024];

/* ---------------- init ---------------- */
__global__ void init_kernel() {
    int t = threadIdx.x;
    if (t < BATCH) { g_junk[t] = 0.0; g_mm[t] = 0.0; }
}

/* ---------------- 3xTF32 tensor-core GEMM: C = act(A[M,K] @ B[K,N] + bias) -------- */
__device__ __forceinline__ void split_tf32(float f, unsigned& hi, unsigned& lo) {
    unsigned h;
    asm("cvt.rna.tf32.f32 %0, %1;" : "=r"(h) : "f"(f));
    float r = f - __uint_as_float(h);
    unsigned l;
    asm("cvt.rna.tf32.f32 %0, %1;" : "=r"(l) : "f"(r));
    hi = h; lo = l;
}

#define MMA_TF32(c, a, b)                                                         \
    asm volatile("mma.sync.aligned.m16n8k8.row.col.f32.tf32.tf32.f32 "            \
                 "{%0,%1,%2,%3},{%4,%5,%6,%7},{%8,%9},{%0,%1,%2,%3};"             \
                 : "+f"((c)[0]), "+f"((c)[1]), "+f"((c)[2]), "+f"((c)[3])         \
                 : "r"((a)[0]), "r"((a)[1]), "r"((a)[2]), "r"((a)[3]),            \
                   "r"((b)[0]), "r"((b)[1]))

template<bool GELU>
__global__ __launch_bounds__(256, 1)
void gemm_tc_kernel(const float* __restrict__ A, const float* __restrict__ B,
                    const float* __restrict__ bias, float* __restrict__ C,
                    int M, int N, int K)
{
    __shared__ float As[128][36];   /* [m][k]  pitch 36: frag reads conflict-free */
    __shared__ float Bs[32][136];   /* [k][n]  pitch 136                          */

    int tid = threadIdx.x;
    int bx = blockIdx.x, by = blockIdx.y;
    int wid = tid >> 5, lane = tid & 31;
    int gid = lane >> 2, tig = lane & 3;
    int warp_m = (wid >> 1) * 32;
    int warp_n = (wid & 1) * 64;

    int arow = tid >> 1,  ak = (tid & 1) * 16;   /* A staging: 128 rows x 32k */
    int brow = tid >> 3,  bc = (tid & 7) * 16;   /* B staging: 32 rows x 128n */

    const float* Ab = A + (size_t)(by * 128 + arow) * K + ak;
    const float* Bb = B + (size_t)brow * N + bx * 128 + bc;

    float c[2][8][4];
#pragma unroll
    for (int mt = 0; mt < 2; ++mt)
#pragma unroll
        for (int nt = 0; nt < 8; ++nt)
#pragma unroll
            for (int q = 0; q < 4; ++q) c[mt][nt][q] = 0.0f;

    float4 pa[4], pb[4];
#pragma unroll
    for (int q = 0; q < 4; ++q) {
        pa[q] = *(const float4*)(Ab + 4 * q);
        pb[q] = *(const float4*)(Bb + 4 * q);
    }

    int iters = K >> 5;
    for (int t = 0; t < iters; ++t) {
#pragma unroll
        for (int q = 0; q < 4; ++q) {
            *(float4*)&As[arow][ak + 4 * q] = pa[q];
            *(float4*)&Bs[brow][bc + 4 * q] = pb[q];
        }
        __syncthreads();

        if (t + 1 < iters) {
            const float* An = Ab + (t + 1) * 32;
            const float* Bn = Bb + (size_t)(t + 1) * 32 * N;
#pragma unroll
            for (int q = 0; q < 4; ++q) {
                pa[q] = *(const float4*)(An + 4 * q);
                pb[q] = *(const float4*)(Bn + 4 * q);
            }
        }

#pragma unroll
        for (int k8 = 0; k8 < 4; ++k8) {
            int kk = k8 * 8;
            unsigned abig[2][4], asml[2][4];
#pragma unroll
            for (int mt = 0; mt < 2; ++mt) {
                int r0 = warp_m + mt * 16 + gid;
                split_tf32(As[r0    ][kk + tig    ], abig[mt][0], asml[mt][0]);
                split_tf32(As[r0 + 8][kk + tig    ], abig[mt][1], asml[mt][1]);
                split_tf32(As[r0    ][kk + tig + 4], abig[mt][2], asml[mt][2]);
                split_tf32(As[r0 + 8][kk + tig + 4], abig[mt][3], asml[mt][3]);
            }
            unsigned bbig[8][2], bsml[8][2];
#pragma unroll
            for (int nt = 0; nt < 8; ++nt) {
                int nn = warp_n + nt * 8 + gid;
                split_tf32(Bs[kk + tig    ][nn], bbig[nt][0], bsml[nt][0]);
                split_tf32(Bs[kk + tig + 4][nn], bbig[nt][1], bsml[nt][1]);
            }
#pragma unroll
            for (int mt = 0; mt < 2; ++mt)
#pragma unroll
                for (int nt = 0; nt < 8; ++nt) {
                    MMA_TF32(c[mt][nt], abig[mt], bbig[nt]);
                    MMA_TF32(c[mt][nt], abig[mt], bsml[nt]);
                    MMA_TF32(c[mt][nt], asml[mt], bbig[nt]);
                }
        }
        __syncthreads();
    }

    /* epilogue: bias (+gelu), direct global stores */
#pragma unroll
    for (int mt = 0; mt < 2; ++mt) {
#pragma unroll
        for (int nt = 0; nt < 8; ++nt) {
            int row = by * 128 + warp_m + mt * 16 + gid;
            int col = bx * 128 + warp_n + nt * 8 + tig * 2;
            float bv0 = bias[col], bv1 = bias[col + 1];
            float v0 = c[mt][nt][0] + bv0;
            float v1 = c[mt][nt][1] + bv1;
            float v2 = c[mt][nt][2] + bv0;
            float v3 = c[mt][nt][3] + bv1;
            if (GELU) {
                v0 = 0.5f * v0 * (1.0f + erff(v0 * 0.70710678118654752440f));
                v1 = 0.5f * v1 * (1.0f + erff(v1 * 0.70710678118654752440f));
                v2 = 0.5f * v2 * (1.0f + erff(v2 * 0.70710678118654752440f));
                v3 = 0.5f * v3 * (1.0f + erff(v3 * 0.70710678118654752440f));
            }
            *(float2*)&C[(size_t)row * N + col]       = make_float2(v0, v1);
            *(float2*)&C[(size_t)(row + 8) * N + col] = make_float2(v2, v3);
        }
    }
}

/* ---------------- LayerNorm (in-place) + dot with w -> logits ---------------- */
__global__ __launch_bounds__(256)
void ln_dot_kernel(float* __restrict__ h, const float* __restrict__ gamma,
                   const float* __restrict__ beta, const float* __restrict__ wv,
                   const float* __restrict__ bsc, float* __restrict__ logits)
{
    __shared__ double red[256];
    int r = blockIdx.x, tid = threadIdx.x;
    float* row = h + (size_t)r * FEAT;
    const int PER = FEAT / 256;   /* 12 */
    float v[PER];
    double s = 0.0;
#pragma unroll
    for (int i = 0; i < PER; ++i) { v[i] = row[tid + i * 256]; s += (double)v[i]; }
    red[tid] = s; __syncthreads();
    for (int o = 128; o > 0; o >>= 1) { if (tid < o) red[tid] += red[tid + o]; __syncthreads(); }
    double mu = red[0] / FEAT;
    __syncthreads();

    double vs = 0.0;
#pragma unroll
    for (int i = 0; i < PER; ++i) { double d = (double)v[i] - mu; vs += d * d; }
    red[tid] = vs; __syncthreads();
    for (int o = 128; o > 0; o >>= 1) { if (tid < o) red[tid] += red[tid + o]; __syncthreads(); }
    float var = (float)(red[0] / FEAT);
    float rstd = rsqrtf(var + 1e-5f);
    float fmu = (float)mu;
    __syncthreads();

    double dot = 0.0;
#pragma unroll
    for (int i = 0; i < PER; ++i) {
        int f = tid + i * 256;
        float y = (v[i] - fmu) * rstd * gamma[f] + beta[f];
        row[f] = y;
        dot += (double)y * (double)wv[f];
    }
    red[tid] = dot; __syncthreads();
    for (int o = 128; o > 0; o >>= 1) { if (tid < o) red[tid] += red[tid + o]; __syncthreads(); }
    if (tid == 0) logits[r] = (float)red[0] + bsc[0];
}

/* ---------------- band joint + fused junk-BCE accumulation ---------------- */
__device__ __forceinline__ float bce0_term(float l) {
    float p = 1.0f / (1.0f + expf(-l));
    float t = -log1pf(-p);
    return fminf(t, 100.0f);
}

__global__ __launch_bounds__(256)
void band_kernel(const int* __restrict__ am)
{
    __shared__ float As[32][33];
    __shared__ float Bs[32][65];
    __shared__ double red[256];

    int b  = blockIdx.y;
    int i0 = blockIdx.x * 32;
    int tid = threadIdx.x;
    const float* Tm = g_temp + (size_t)b * SEQ * FEAT;
    const float* En = g_end  + (size_t)b * SEQ * FEAT;

    int ar  = tid >> 3;
    int ac4 = tid & 7;
    int r  = tid & 31;
    int cb = (tid >> 5) * 8;

    float acc[8];
#pragma unroll
    for (int i = 0; i < 8; ++i) acc[i] = 0.0f;

    for (int k0 = 0; k0 < FEAT; k0 += 32) {
        float4 a = *(const float4*)(Tm + (size_t)(i0 + ar) * FEAT + k0 + ac4 * 4);
        As[ac4*4+0][ar] = a.x; As[ac4*4+1][ar] = a.y;
        As[ac4*4+2][ar] = a.z; As[ac4*4+3][ar] = a.w;
#pragma unroll
        for (int h = 0; h < 2; ++h) {
            int row = ar + h * 32;
            int j = i0 + row;
            float4 bv = make_float4(0.f, 0.f, 0.f, 0.f);
            if (j < SEQ) bv = *(const float4*)(En + (size_t)j * FEAT + k0 + ac4 * 4);
            Bs[ac4*4+0][row] = bv.x; Bs[ac4*4+1][row] = bv.y;
            Bs[ac4*4+2][row] = bv.z; Bs[ac4*4+3][row] = bv.w;
        }
        __syncthreads();
#pragma unroll
        for (int k = 0; k < 32; ++k) {
            float av = As[k][r];
#pragma unroll
            for (int cc = 0; cc < 8; ++cc)
                acc[cc] = fmaf(av, Bs[k][cb + cc], acc[cc]);
        }
        __syncthreads();
    }

    int i = i0 + r;
    float sli = g_sl[b * SEQ + i];
    int ami = am[b * SEQ + i];
    double tsum = 0.0, wsum = 0.0;
    const float NEGINF = __int_as_float(0xff800000);
#pragma unroll
    for (int cc = 0; cc < 8; ++cc) {
        int ccn = cb + cc;
        int d = ccn - r;
        int j = i0 + ccn;
        if (d >= 0 && d < BANDW) {
            float val = NEGINF;
            if (d < MAX_SPAN_LEN && j < SEQ) {
                float l = acc[cc] + sli + g_el[b * SEQ + j];
                l = fminf(fmaxf(l, -10000.0f), 10000.0f);
                val = l;
                float w = (float)(ami * am[b * SEQ + j]);
                tsum += (double)(bce0_term(l) * w);
                wsum += (double)w;
            }
            g_band[((size_t)b * SEQ + i) * BANDW + d] = val;
        }
    }
    red[tid] = tsum; __syncthreads();
    for (int o = 128; o > 0; o >>= 1) { if (tid < o) red[tid] += red[tid + o]; __syncthreads(); }
    if (tid == 0) atomicAdd(&g_junk[b], red[0]);
    __syncthreads();
    red[tid] = wsum; __syncthreads();
    for (int o = 128; o > 0; o >>= 1) { if (tid < o) red[tid] += red[tid + o]; __syncthreads(); }
    if (tid == 0) atomicAdd(&g_mm[b], red[0]);
}

/* ---------------- exact top-k (radix select) + sort + index outputs ---------------- */
__device__ __forceinline__ unsigned f2ord(float f) {
    unsigned u = __float_as_uint(f);
    return (u & 0x80000000u) ? ~u : (u | 0x80000000u);
}

__global__ __launch_bounds__(1024)
void select_kernel(const int* __restrict__ am, float* __restrict__ out)
{
    int b = blockIdx.x;
    int tid = threadIdx.x;
    const float* band = g_band + (size_t)b * SEQ * BANDW;
    const int N = SEQ * BANDW;

    __shared__ unsigned hist[256];
    __shared__ unsigned s_prefix, s_rem;
    __shared__ int arr[1024];
    __shared__ int s_nA, s_nE;

    int ls = 0;
    for (int i = tid; i < SEQ; i += 1024) ls += am[b * SEQ + i];
    arr[tid] = ls; __syncthreads();
    for (int o = 512; o > 0; o >>= 1) { if (tid < o) arr[tid] += arr[tid + o]; __syncthreads(); }
    int lens = arr[0];
    __syncthreads();
    int k = (int)((float)lens * 0.2f);
    if (k > MAXK) k = MAXK;
    if (k < 0) k = 0;

    unsigned prefix = 0, rem = (unsigned)k;
    for (int shift = 24; shift >= 0; shift -= 8) {
        if (tid < 256) hist[tid] = 0u;
        __syncthreads();
        for (int idx = tid; idx < N; idx += 1024) {
            unsigned u = f2ord(band[idx]);
            if (shift == 24 || (u >> (shift + 8)) == (prefix >> (shift + 8)))
                atomicAdd(&hist[(u >> shift) & 255u], 1u);
        }
        __syncthreads();
        if (tid == 0) {
            unsigned remv = rem, pf = prefix;
            for (int bin = 255; bin >= 0; --bin) {
                unsigned cq = hist[bin];
                if (cq >= remv) { pf |= ((unsigned)bin) << shift; break; }
                remv -= cq;
            }
            s_prefix = pf; s_rem = remv;
        }
        __syncthreads();
        prefix = s_prefix; rem = s_rem;
        __syncthreads();
    }
    unsigned thr = prefix;

    if (tid == 0) { s_nA = 0; s_nE = 0; }
    __syncthreads();
    for (int idx = tid; idx < N; idx += 1024) {
        unsigned u = f2ord(band[idx]);
        if (u > thr) {
            int p = atomicAdd(&s_nA, 1);
            if (p < 2048) {
                int i = idx >> 5, d = idx & 31;
                g_selbuf[b][p] = i * SEQ + i + d;
            }
        } else if (u == thr) {
            int p = atomicAdd(&s_nE, 1);
            if (p < 1024) {
                int i = idx >> 5, d = idx & 31;
                g_eqbuf[b][p] = i * SEQ + i + d;
            }
        }
    }
    __syncthreads();
    int nA = s_nA;
    int need = k - nA;
    if (tid == 0 && need > 0) {
        int ne = s_nE; if (ne > 1024) ne = 1024;
        for (int t = 0; t < need; ++t) {
            int best = -1, bv = 0x7fffffff;
            for (int q = 0; q < ne; ++q) {
                int v = g_eqbuf[b][q];
                if (v < bv) { bv = v; best = q; }
            }
            if (best >= 0) { g_eqbuf[b][best] = 0x7fffffff; g_selbuf[b][nA + t] = bv; }
        }
    }
    __syncthreads();

    arr[tid] = (tid < k) ? g_selbuf[b][tid]
             : ((tid < MAXK) ? (SEQ * SEQ - 1) : 0x7fffffff);
    __syncthreads();
    for (unsigned kk = 2; kk <= 1024; kk <<= 1) {
        for (unsigned j = kk >> 1; j > 0; j >>= 1) {
            unsigned ixj = tid ^ j;
            if (ixj > (unsigned)tid) {
                int a0 = arr[tid], a1 = arr[ixj];
                bool up = ((tid & kk) == 0);
                if ((a0 > a1) == up) { arr[tid] = a1; arr[ixj] = a0; }
            }
            __syncthreads();
        }
    }
    if (tid < MAXK) {
        int v = arr[tid];
        if (v == SEQ * SEQ - 1) v = 0;
        out[OFF_STARTS + b * MAXK + tid] = (float)(v / SEQ);
        out[OFF_ENDS   + b * MAXK + tid] = (float)(v % SEQ);
        out[OFF_MASK   + b * MAXK + tid] = (tid < k) ? 1.0f : 0.0f;
    }
}

/* ---------------- gold cost + junk adjustment -> cost_is_mention ---------------- */
__global__ void gold_kernel(const void* __restrict__ gold_raw,
                            const float* __restrict__ gm_mask,
                            const int* __restrict__ am,
                            float* __restrict__ out)
{
    if (threadIdx.x != 0) return;
    int b = blockIdx.x;
    const int* g32 = (const int*)gold_raw;
    const long long* g64 = (const long long*)gold_raw;

    bool is64 = true;
    for (int w = 1; w < 200; w += 2) if (g32[w] != 0) { is64 = false; break; }

    int gs[NGOLD], ge[NGOLD];
    long long tot = 0;
    for (int g = 0; g < NGOLD; ++g) {
        int base = (b * NGOLD + g) * 2;
        long long a, e;
        if (is64) { a = g64[base]; e = g64[base + 1]; }
        else      { a = g32[base]; e = g32[base + 1]; }
        gs[g] = (int)a; ge[g] = (int)e; tot += a + e;
    }
    bool has_gold = (tot > 0);

    double gsum = 0.0, gmsum = 0.0;
    for (int g = 0; g < NGOLD; ++g) {
        float gmv = gm_mask[b * NGOLD + g];
        gmsum += (double)gmv;
        float term;
        if (gmv != 0.0f) {
            int d = ge[g] - gs[g];
            if (d >= 0 && d < MAX_SPAN_LEN) {
                float l = g_band[((size_t)b * SEQ + gs[g]) * BANDW + d];
                float p = (1.0f / (1.0f + expf(-l))) * gmv;
                float lp = logf(p);
                term = fminf(-lp, 100.0f);
            } else {
                term = 100.0f;
            }
        } else term = 0.0f;
        gsum += (double)term;
    }
    double cost_gold = (has_gold && gmsum > 0.0) ? gsum / gmsum : 0.0;

    double sub = 0.0;
    if (has_gold) {
        for (int g = 0; g < NGOLD; ++g) {
            int d = ge[g] - gs[g];
            if (d < 0 || d >= MAX_SPAN_LEN) continue;
            if (gs[g] == 0 && ge[g] == 0) continue;
            bool dup = false;
            for (int q = 0; q < g; ++q)
                if (gs[q] == gs[g] && ge[q] == ge[g]) { dup = true; break; }
            if (dup) continue;
            float l = g_band[((size_t)b * SEQ + gs[g]) * BANDW + d];
            float w = (float)(am[b * SEQ + gs[g]] * am[b * SEQ + ge[g]]);
            sub += (double)(bce0_term(l) * w);
        }
    }
    double cost_junk = (g_junk[b] - sub) / g_mm[b];
    out[OFF_COST + b] = (float)(cost_gold + cost_junk);
}

/* ---------------- host launcher ---------------- */
extern "C" void kernel_launch(void* const* d_in, const int* in_sizes, int n_in,
                              void* d_out, int out_size)
{
    const float* seq     = (const float*)d_in[0];
    const int*   am      = (const int*)  d_in[1];
    const void*  gold    =               d_in[2];
    const float* gmask   = (const float*)d_in[3];
    const float* Ws      = (const float*)d_in[4];
    const float* bs      = (const float*)d_in[5];
    const float* gsv     = (const float*)d_in[6];
    const float* betas   = (const float*)d_in[7];
    const float* We      = (const float*)d_in[8];
    const float* be      = (const float*)d_in[9];
    const float* gev     = (const float*)d_in[10];
    const float* betae   = (const float*)d_in[11];
    const float* w_start = (const float*)d_in[12];
    const float* b_start = (const float*)d_in[13];
    const float* w_end   = (const float*)d_in[14];
    const float* b_end   = (const float*)d_in[15];
    const float* W_s2e   = (const float*)d_in[16];
    const float* b_s2e   = (const float*)d_in[17];
    float* out = (float*)d_out;

    float *pstart, *pend, *ptemp, *psl, *pel;
    cudaGetSymbolAddress((void**)&pstart, g_start);
    cudaGetSymbolAddress((void**)&pend,   g_end);
    cudaGetSymbolAddress((void**)&ptemp,  g_temp);
    cudaGetSymbolAddress((void**)&psl,    g_sl);
    cudaGetSymbolAddress((void**)&pel,    g_el);

    init_kernel<<<1, 32>>>();

    dim3 gg(FEAT / 128, ROWS / 128);
    gemm_tc_kernel<true><<<gg, 256>>>(seq, Ws, bs, pstart, ROWS, FEAT, HID);
    gemm_tc_kernel<true><<<gg, 256>>>(seq, We, be, pend,   ROWS, FEAT, HID);

    ln_dot_kernel<<<ROWS, 256>>>(pstart, gsv, betas, w_start, b_start, psl);
    ln_dot_kernel<<<ROWS, 256>>>(pend,   gev, betae, w_end,   b_end,   pel);

    gemm_tc_kernel<false><<<gg, 256>>>(pstart, W_s2e, b_s2e, ptemp, ROWS, FEAT, FEAT);

    band_kernel<<<dim3(SEQ / 32, BATCH), 256>>>(am);
    select_kernel<<<BATCH, 1024>>>(am, out);
    gold_kernel<<<BATCH, 1>>>(gold, gmask, am, out);

    cudaMemcpyAsync(out + OFF_SEQ, seq, (size_t)ROWS * HID * sizeof(float),
                    cudaMemcpyDeviceToDevice, 0);
}